// round 1
// baseline (speedup 1.0000x reference)
#include <cuda_runtime.h>
#include <cstdint>

// VQ-VAE vector quantizer:
//   z_e:      [32, 64, 64, 64] fp32  (B, C, H, W)  -> in_sizes[0] = 8388608
//   codebook: [512, 64] fp32                        -> in_sizes[1] = 32768
// Output (concatenated in d_out, fp32):
//   z_q:     [32, 64, 64, 64] = 8388608 elems
//   indices: [131072] (written as float values) if out_size covers them.

#define NUM_K 512
#define DIM_C 64
#define HW    4096           // 64*64
#define N_PTS 131072         // 32*64*64
#define ZQ_ELEMS 8388608

__device__ float g_csq[NUM_K];

// ---------------------------------------------------------------------------
// Kernel 1: per-code squared norms, correctly rounded (fp64 accumulate).
// ---------------------------------------------------------------------------
__global__ void vq_csq_kernel(const float* __restrict__ cb) {
    int k = threadIdx.x;   // one block of 512 threads
    const float4* row = reinterpret_cast<const float4*>(cb + k * DIM_C);
    double s = 0.0;
    #pragma unroll
    for (int i = 0; i < DIM_C / 4; i++) {
        float4 v = row[i];
        s += (double)v.x * v.x + (double)v.y * v.y
           + (double)v.z * v.z + (double)v.w * v.w;
    }
    g_csq[k] = (float)s;
}

// ---------------------------------------------------------------------------
// Kernel 2: per-point argmin over 512 codes + gather/scatter of z_q.
// One thread = one point; z row (64 fp32) lives in registers; codebook is
// read via uniform-address LDG.128 (warp-broadcast, L1/L2 resident: 128 KB).
// Distance formula mirrors the reference's rounding:
//   d = fl( fl(zsq + csq[k]) - 2*dot )   (2*dot is exact; FMA-safe)
// Strict '<' keeps the lowest index on ties, matching argmin semantics.
// ---------------------------------------------------------------------------
__global__ __launch_bounds__(256, 2) void vq_main_kernel(
    const float* __restrict__ z,
    const float* __restrict__ cb,
    float* __restrict__ out,
    int write_idx)
{
    int n = blockIdx.x * 256 + threadIdx.x;
    int b  = n >> 12;          // n / 4096
    int hw = n & 4095;

    const float* zp = z + (size_t)b * (DIM_C * HW) + hw;

    // Load this point's channel vector (stride HW between channels;
    // consecutive lanes -> consecutive addresses: fully coalesced).
    float zr[DIM_C];
    #pragma unroll
    for (int c = 0; c < DIM_C; c++) zr[c] = zp[(size_t)c * HW];

    // ||z||^2, correctly rounded (one-time fp64 cost, negligible).
    double zs = 0.0;
    #pragma unroll
    for (int c = 0; c < DIM_C; c++) zs += (double)zr[c] * (double)zr[c];
    float zsq = (float)zs;

    const float4* cb4 = reinterpret_cast<const float4*>(cb);

    float best  = 3.402823466e38f;
    int   bestk = 0;

    #pragma unroll 1
    for (int k = 0; k < NUM_K; k++) {
        float d0 = 0.f, d1 = 0.f, d2 = 0.f, d3 = 0.f;   // ILP-4 FMA chains
        #pragma unroll
        for (int i = 0; i < DIM_C / 4; i++) {
            float4 cv = __ldg(&cb4[k * (DIM_C / 4) + i]);
            d0 = fmaf(zr[4 * i + 0], cv.x, d0);
            d1 = fmaf(zr[4 * i + 1], cv.y, d1);
            d2 = fmaf(zr[4 * i + 2], cv.z, d2);
            d3 = fmaf(zr[4 * i + 3], cv.w, d3);
        }
        float dot = (d0 + d1) + (d2 + d3);
        float t   = __fadd_rn(zsq, g_csq[k]);
        float d   = __fadd_rn(t, -2.0f * dot);          // 2*dot exact in fp32
        if (d < best) { best = d; bestk = k; }
    }

    // Scatter the selected code row back into [B, C, H, W] layout.
    float* op = out + (size_t)b * (DIM_C * HW) + hw;
    const float* crow = cb + bestk * DIM_C;
    #pragma unroll
    for (int c = 0; c < DIM_C; c++) op[(size_t)c * HW] = __ldg(&crow[c]);

    if (write_idx) out[ZQ_ELEMS + n] = (float)bestk;
}

// ---------------------------------------------------------------------------
extern "C" void kernel_launch(void* const* d_in, const int* in_sizes, int n_in,
                              void* d_out, int out_size) {
    const float* z  = (const float*)d_in[0];
    const float* cb = (const float*)d_in[1];
    float* out = (float*)d_out;

    int write_idx = (out_size >= ZQ_ELEMS + N_PTS) ? 1 : 0;

    vq_csq_kernel<<<1, NUM_K>>>(cb);
    vq_main_kernel<<<N_PTS / 256, 256>>>(z, cb, out, write_idx);
}

// round 2
// speedup vs baseline: 1.1189x; 1.1189x over previous
#include <cuda_runtime.h>
#include <cstdint>

// VQ-VAE vector quantizer on GB300.
//   z_e:      [32, 64, 64, 64] fp32  (B, C, H, W)
//   codebook: [512, 64] fp32
// d_out fp32: z_q (8388608 elems) then indices (131072, as float).

#define NUM_K 512
#define DIM_C 64
#define HW    4096
#define N_PTS 131072
#define ZQ_ELEMS 8388608
#define TILE_K 128            // codes per smem tile (32 KB)
#define NUM_TILES (NUM_K / TILE_K)

__device__ float g_csq[NUM_K];

// Packed fp32x2 helpers (Blackwell sm_103a; PTX-only instructions).
#define FMA_F32X2(d, a, b, c) \
    asm("fma.rn.f32x2 %0, %1, %2, %3;" : "=l"(d) : "l"(a), "l"(b), "l"(c))
#define ADD_F32X2_(d, a, b) \
    asm("add.rn.f32x2 %0, %1, %2;" : "=l"(d) : "l"(a), "l"(b))
#define PACK_F32X2_(d, lo, hi) \
    asm("mov.b64 %0, {%1, %2};" : "=l"(d) : "f"(lo), "f"(hi))
#define UNPACK_F32X2_(lo, hi, s) \
    asm("mov.b64 {%0, %1}, %2;" : "=f"(lo), "=f"(hi) : "l"(s))

// ---------------------------------------------------------------------------
// Kernel 1: per-code squared norms (fp64 accumulate, correctly rounded).
// ---------------------------------------------------------------------------
__global__ void vq_csq_kernel(const float* __restrict__ cb) {
    int k = threadIdx.x;   // 512 threads
    const float4* row = reinterpret_cast<const float4*>(cb + k * DIM_C);
    double s = 0.0;
    #pragma unroll
    for (int i = 0; i < DIM_C / 4; i++) {
        float4 v = row[i];
        s += (double)v.x * v.x + (double)v.y * v.y
           + (double)v.z * v.z + (double)v.w * v.w;
    }
    g_csq[k] = (float)s;
}

// ---------------------------------------------------------------------------
// Kernel 2: argmin over 512 codes, one thread per point.
// Codebook streamed through 32KB smem tiles (LDS broadcast, floor 2cyc);
// dot products via packed fma.rn.f32x2 (2 MACs/instr, 2x fp32 throughput).
// ---------------------------------------------------------------------------
__global__ __launch_bounds__(256, 2) void vq_main_kernel(
    const float* __restrict__ z,
    const float* __restrict__ cb,
    float* __restrict__ out,
    int write_idx)
{
    __shared__ float s_cb[TILE_K * DIM_C];   // 32 KB
    __shared__ float s_csq[TILE_K];

    const int tid = threadIdx.x;
    const int n   = blockIdx.x * 256 + tid;
    const int b   = n >> 12;
    const int hw  = n & 4095;

    const float* zp = z + (size_t)b * (DIM_C * HW) + hw;

    // Load this point's 64 channels (coalesced across lanes), pack to f32x2.
    unsigned long long zpk[DIM_C / 2];
    double zs = 0.0;
    #pragma unroll
    for (int i = 0; i < DIM_C / 2; i++) {
        float lo = zp[(size_t)(2 * i)     * HW];
        float hi = zp[(size_t)(2 * i + 1) * HW];
        PACK_F32X2_(zpk[i], lo, hi);
        zs += (double)lo * lo + (double)hi * hi;
    }
    const float zsq = (float)zs;

    float best  = 3.402823466e38f;
    int   bestk = 0;

    const float4* cb4 = reinterpret_cast<const float4*>(cb);
    float4* s_cb4 = reinterpret_cast<float4*>(s_cb);

    for (int t = 0; t < NUM_TILES; t++) {
        __syncthreads();  // previous tile fully consumed
        // Cooperative tile load: 8192 floats = 2048 float4, 8 per thread.
        #pragma unroll
        for (int j = 0; j < 8; j++) {
            int i = tid + j * 256;
            s_cb4[i] = cb4[t * (TILE_K * DIM_C / 4) + i];
        }
        if (tid < TILE_K) s_csq[tid] = g_csq[t * TILE_K + tid];
        __syncthreads();

        #pragma unroll 1
        for (int k = 0; k < TILE_K; k++) {
            const ulonglong2* row =
                reinterpret_cast<const ulonglong2*>(s_cb + k * DIM_C);
            unsigned long long a0 = 0, a1 = 0, a2 = 0, a3 = 0;
            #pragma unroll
            for (int i = 0; i < DIM_C / 4; i++) {      // 16 x LDS.128
                ulonglong2 cv = row[i];                // pairs (4i,4i+1),(4i+2,4i+3)
                if ((i & 1) == 0) {
                    FMA_F32X2(a0, cv.x, zpk[2 * i],     a0);
                    FMA_F32X2(a1, cv.y, zpk[2 * i + 1], a1);
                } else {
                    FMA_F32X2(a2, cv.x, zpk[2 * i],     a2);
                    FMA_F32X2(a3, cv.y, zpk[2 * i + 1], a3);
                }
            }
            unsigned long long s01, s23, s;
            ADD_F32X2_(s01, a0, a1);
            ADD_F32X2_(s23, a2, a3);
            ADD_F32X2_(s, s01, s23);
            float lo, hi;
            UNPACK_F32X2_(lo, hi, s);
            float dot = lo + hi;
            float d = __fadd_rn(__fadd_rn(zsq, s_csq[k]), -2.0f * dot);
            if (d < best) { best = d; bestk = t * TILE_K + k; }
        }
    }

    // Scatter chosen code row back into [B, C, H, W] layout.
    float* op = out + (size_t)b * (DIM_C * HW) + hw;
    const float* crow = cb + bestk * DIM_C;
    #pragma unroll
    for (int c = 0; c < DIM_C; c++) op[(size_t)c * HW] = __ldg(&crow[c]);

    if (write_idx) out[ZQ_ELEMS + n] = (float)bestk;
}

// ---------------------------------------------------------------------------
extern "C" void kernel_launch(void* const* d_in, const int* in_sizes, int n_in,
                              void* d_out, int out_size) {
    const float* z  = (const float*)d_in[0];
    const float* cb = (const float*)d_in[1];
    float* out = (float*)d_out;

    int write_idx = (out_size >= ZQ_ELEMS + N_PTS) ? 1 : 0;

    vq_csq_kernel<<<1, NUM_K>>>(cb);
    vq_main_kernel<<<N_PTS / 256, 256>>>(z, cb, out, write_idx);
}

// round 6
// speedup vs baseline: 2.1174x; 1.8924x over previous
#include <cuda_runtime.h>
#include <cstdint>

// VQ-VAE vector quantizer on GB300 — register-tiled SIMT GEMM + argmin.
//   z_e:      [32, 64, 64, 64] fp32  (B, C, H, W)
//   codebook: [512, 64] fp32
// d_out fp32: z_q (8388608) then indices (131072, stored as float).

#define NUM_K 512
#define DIM_C 64
#define HW    4096
#define N_PTS 131072
#define ZQ_ELEMS 8388608
#define PTS_CTA 128
#define KTILE   128
#define NTILES  (NUM_K / KTILE)

// Shared-memory arena layout (bytes).
#define OFF_Z    0                    // dup'd z tile: 64 c * 256 floats = 65536
#define OFF_CBT  65536                // cbT tile [64 c][128 k]        = 32768
#define OFF_RED  65536                // reduction area (reuses cbT)
#define OFF_CSQ  (65536 + 32768)      // 512 floats  = 2048
#define OFF_ZSQ  (OFF_CSQ + 2048)     // 128 floats  = 512
#define ARENA_BYTES (OFF_ZSQ + 512)   // 100864

// 128B-periodic XOR swizzle (spreads stride-64B accesses across banks).
#define SWZ(o) ((o) ^ ((((unsigned)(o)) >> 3) & 0x70u))

// Packed fp32x2 (Blackwell-only PTX).
#define FMA_F32X2(d, a, b, c) \
    asm("fma.rn.f32x2 %0, %1, %2, %3;" : "=l"(d) : "l"(a), "l"(b), "l"(c))
#define UNPACK_F32X2_(lo, hi, s) \
    asm("mov.b64 {%0, %1}, %2;" : "=f"(lo), "=f"(hi) : "l"(s))

__device__ float g_csq[NUM_K];

// ---------------------------------------------------------------------------
// Kernel 1: per-code squared norms (fp64 accumulate, correctly rounded).
// ---------------------------------------------------------------------------
__global__ void vq_csq_kernel(const float* __restrict__ cb) {
    int k = threadIdx.x;   // 512 threads
    const float4* row = reinterpret_cast<const float4*>(cb + k * DIM_C);
    double s = 0.0;
    #pragma unroll
    for (int i = 0; i < DIM_C / 4; i++) {
        float4 v = row[i];
        s += (double)v.x * v.x + (double)v.y * v.y
           + (double)v.z * v.z + (double)v.w * v.w;
    }
    g_csq[k] = (float)s;
}

// ---------------------------------------------------------------------------
// Kernel 2: tiled GEMM + argmin. 256 threads, 8pt x 8code register tile.
// ---------------------------------------------------------------------------
__global__ __launch_bounds__(256, 2) void vq_gemm_kernel(
    const float* __restrict__ z,
    const float* __restrict__ cb,
    float* __restrict__ out,
    int write_idx)
{
    extern __shared__ char arena[];
    float* s_cbt = reinterpret_cast<float*>(arena + OFF_CBT);
    float* s_csq = reinterpret_cast<float*>(arena + OFF_CSQ);
    float* s_zsq = reinterpret_cast<float*>(arena + OFF_ZSQ);
    float* s_rd  = reinterpret_cast<float*>(arena + OFF_RED);
    int*   s_rk  = reinterpret_cast<int*>  (arena + OFF_RED + PTS_CTA * 17 * 4);

    const int tid  = threadIdx.x;
    const int pcol = tid & 15;        // point group 0..15
    const int trow = tid >> 4;        // code group  0..15
    const int p0   = pcol * 8;

    const int n0  = blockIdx.x * PTS_CTA;
    const int b   = n0 >> 12;
    const int hw0 = n0 & 4095;
    const float* zb = z + (size_t)b * (DIM_C * HW) + hw0;

    // ---- Load z tile, duplicated ({z,z} pairs) + swizzled. ----
    {
        int c = tid >> 2, q = tid & 3;
        const float4* src = reinterpret_cast<const float4*>(zb + (size_t)c * HW + q * 32);
        #pragma unroll
        for (int j = 0; j < 8; j++) {
            float4 v = src[j];
            int base = c * 1024 + (q * 32 + 4 * j) * 8;
            float4 d0 = make_float4(v.x, v.x, v.y, v.y);
            float4 d1 = make_float4(v.z, v.z, v.w, v.w);
            *reinterpret_cast<float4*>(arena + SWZ(base))      = d0;
            *reinterpret_cast<float4*>(arena + SWZ(base + 16)) = d1;
        }
    }
    // csq -> smem
    s_csq[tid]       = g_csq[tid];
    s_csq[tid + 256] = g_csq[tid + 256];
    __syncthreads();

    // ---- zsq per point (fp64, correctly rounded). 2 threads/point. ----
    {
        int p = tid >> 1, half = tid & 1;
        double s = 0.0;
        for (int c = half * 32; c < half * 32 + 32; c++) {
            float v = *reinterpret_cast<const float*>(arena + SWZ(c * 1024 + p * 8));
            s += (double)v * v;
        }
        double o = __shfl_xor_sync(0xffffffffu, s, 1);
        if (half == 0) s_zsq[p] = (float)(s + o);
    }
    // (visibility of s_zsq covered by the sync inside the tile loop)

    float best[8];
    int   bk[8];
    #pragma unroll
    for (int i = 0; i < 8; i++) { best[i] = 3.402823466e38f; bk[i] = 0; }

    for (int t = 0; t < NTILES; t++) {
        __syncthreads();
        // ---- Load + transpose cbT tile [64 c][128 k]. ----
        {
            int k = tid & 127, chalf = tid >> 7;
            const float4* crow =
                reinterpret_cast<const float4*>(cb + (size_t)(t * KTILE + k) * DIM_C + chalf * 32);
            #pragma unroll
            for (int j = 0; j < 8; j++) {
                float4 v = crow[j];
                int c = chalf * 32 + 4 * j;
                s_cbt[(c + 0) * 128 + k] = v.x;
                s_cbt[(c + 1) * 128 + k] = v.y;
                s_cbt[(c + 2) * 128 + k] = v.z;
                s_cbt[(c + 3) * 128 + k] = v.w;
            }
        }
        __syncthreads();

        unsigned long long acc[8][4];
        #pragma unroll
        for (int p = 0; p < 8; p++)
            #pragma unroll
            for (int q2 = 0; q2 < 4; q2++) acc[p][q2] = 0ull;

        const char* cbbase = arena + OFF_CBT + trow * 32;

        #pragma unroll 4
        for (int c = 0; c < DIM_C; c++) {
            ulonglong2 b01 = *reinterpret_cast<const ulonglong2*>(cbbase + c * 512);
            ulonglong2 b23 = *reinterpret_cast<const ulonglong2*>(cbbase + c * 512 + 16);
            ulonglong2 zz[4];
            #pragma unroll
            for (int q = 0; q < 4; q++) {
                int off = c * 1024 + pcol * 64 + q * 16;
                zz[q] = *reinterpret_cast<const ulonglong2*>(arena + SWZ(off));
            }
            #pragma unroll
            for (int p = 0; p < 8; p++) {
                unsigned long long a = (p & 1) ? zz[p >> 1].y : zz[p >> 1].x;
                FMA_F32X2(acc[p][0], a, b01.x, acc[p][0]);
                FMA_F32X2(acc[p][1], a, b01.y, acc[p][1]);
                FMA_F32X2(acc[p][2], a, b23.x, acc[p][2]);
                FMA_F32X2(acc[p][3], a, b23.y, acc[p][3]);
            }
        }

        // ---- Per-tile argmin epilogue (k-ascending within thread). ----
        int kb = t * KTILE + trow * 8;
        #pragma unroll
        for (int q2 = 0; q2 < 4; q2++) {
            float cs0 = s_csq[kb + 2 * q2];
            float cs1 = s_csq[kb + 2 * q2 + 1];
            #pragma unroll
            for (int p = 0; p < 8; p++) {
                float dlo, dhi;
                UNPACK_F32X2_(dlo, dhi, acc[p][q2]);
                float zq = s_zsq[p0 + p];
                float d0 = __fadd_rn(__fadd_rn(zq, cs0), -2.0f * dlo);
                float d1 = __fadd_rn(__fadd_rn(zq, cs1), -2.0f * dhi);
                if (d0 < best[p]) { best[p] = d0; bk[p] = kb + 2 * q2; }
                if (d1 < best[p]) { best[p] = d1; bk[p] = kb + 2 * q2 + 1; }
            }
        }
    }

    // ---- Cross-thread reduction over the 16 code-rows. ----
    __syncthreads();                    // done with cbT; reuse as reduction area
    #pragma unroll
    for (int i = 0; i < 8; i++) {
        s_rd[(p0 + i) * 17 + trow] = best[i];
        s_rk[(p0 + i) * 17 + trow] = bk[i];
    }
    __syncthreads();

    if (tid < PTS_CTA) {
        int p = tid;
        float bd = s_rd[p * 17];
        int   bkk = s_rk[p * 17];
        #pragma unroll
        for (int r = 1; r < 16; r++) {
            float d = s_rd[p * 17 + r];
            int   k = s_rk[p * 17 + r];
            if (d < bd || (d == bd && k < bkk)) { bd = d; bkk = k; }
        }
        // Scatter selected code row into [B, C, H, W].
        float* op = out + (size_t)b * (DIM_C * HW) + hw0 + p;
        const float4* crow = reinterpret_cast<const float4*>(cb + (size_t)bkk * DIM_C);
        #pragma unroll
        for (int i = 0; i < 16; i++) {
            float4 v = __ldg(&crow[i]);
            op[(size_t)(4 * i + 0) * HW] = v.x;
            op[(size_t)(4 * i + 1) * HW] = v.y;
            op[(size_t)(4 * i + 2) * HW] = v.z;
            op[(size_t)(4 * i + 3) * HW] = v.w;
        }
        if (write_idx) out[ZQ_ELEMS + n0 + p] = (float)bkk;
    }
}

// ---------------------------------------------------------------------------
extern "C" void kernel_launch(void* const* d_in, const int* in_sizes, int n_in,
                              void* d_out, int out_size) {
    const float* z  = (const float*)d_in[0];
    const float* cb = (const float*)d_in[1];
    float* out = (float*)d_out;

    int write_idx = (out_size >= ZQ_ELEMS + N_PTS) ? 1 : 0;

    cudaFuncSetAttribute(vq_gemm_kernel,
                         cudaFuncAttributeMaxDynamicSharedMemorySize, ARENA_BYTES);

    vq_csq_kernel<<<1, NUM_K>>>(cb);
    vq_gemm_kernel<<<N_PTS / PTS_CTA, 256, ARENA_BYTES>>>(z, cb, out, write_idx);
}

// round 11
// speedup vs baseline: 2.1559x; 1.0182x over previous
#include <cuda_runtime.h>
#include <cuda_fp16.h>
#include <cstdint>

// VQ-VAE vector quantizer on GB300 — HMMA fp16-split GEMM + argmin,
// with margin-gated exact fp32 rescore for near-tie points.
//   z_e:      [32, 64, 64, 64] fp32  (B, C, H, W)
//   codebook: [512, 64] fp32
// d_out fp32: z_q (8388608) then indices (131072, stored as float).

#define NUM_K 512
#define DIM_C 64
#define HW    4096
#define N_PTS 131072
#define ZQ_ELEMS 8388608
#define PTS_TILE 128
#define NTILES   (N_PTS / PTS_TILE)
#define GRID_MAIN 148
#define THRESH 6e-5f

// smem offsets from 1024-aligned base
#define OFF_AH   0          // A_hi 128x64 fp16 SW128 : 16384
#define OFF_AL   16384      // A_lo                    : 16384
#define OFF_BH   32768      // B_hi 512x64 fp16 SW128  : 65536
#define OFF_BL   98304      // B_lo                    : 65536
#define OFF_ZST  163840     // fp32 z stage [64c][128p]: 32768
#define OFF_CSQ  196608     // 512 f  : 2048
#define OFF_ZSQ  198656     // 128 f  : 512
#define OFF_RD   199168     // 128x4 f: 2048
#define OFF_R2   201216     // 128x4 f: 2048
#define OFF_RK   203264     // 128x4 i: 2048
#define OFF_BK   205312     // 128 i  : 512
#define OFF_FLG  205824     // cnt + 128 i : 520
#define SMEM_BYTES (206848 + 1024)

#define SWZ128(o) ((o) ^ ((((unsigned)(o)) >> 3) & 0x70u))

__device__ __forceinline__ uint32_t smem_u32(const void* p) {
    uint32_t a;
    asm("{ .reg .u64 t; cvta.to.shared.u64 t, %1; cvt.u32.u64 %0, t; }" : "=r"(a) : "l"(p));
    return a;
}
__device__ __forceinline__ void ldsm_x4(uint32_t* a, uint32_t addr) {
    asm volatile("ldmatrix.sync.aligned.m8n8.x4.shared.b16 {%0,%1,%2,%3}, [%4];"
        : "=r"(a[0]), "=r"(a[1]), "=r"(a[2]), "=r"(a[3]) : "r"(addr));
}
__device__ __forceinline__ void ldsm_x2(uint32_t* a, uint32_t addr) {
    asm volatile("ldmatrix.sync.aligned.m8n8.x2.shared.b16 {%0,%1}, [%2];"
        : "=r"(a[0]), "=r"(a[1]) : "r"(addr));
}
__device__ __forceinline__ void mma16816(float* c, const uint32_t* a, const uint32_t* b) {
    asm volatile("mma.sync.aligned.m16n8k16.row.col.f32.f16.f16.f32 "
        "{%0,%1,%2,%3}, {%4,%5,%6,%7}, {%8,%9}, {%0,%1,%2,%3};"
        : "+f"(c[0]), "+f"(c[1]), "+f"(c[2]), "+f"(c[3])
        : "r"(a[0]), "r"(a[1]), "r"(a[2]), "r"(a[3]), "r"(b[0]), "r"(b[1]));
}
__device__ __forceinline__ uint32_t addr_A(uint32_t tb, int m0, int k0, int lane) {
    int r = lane & 7, sel = lane >> 3;
    int row = m0 + r + ((sel & 1) << 3);
    uint32_t off = (uint32_t)(row * 128 + (k0 + ((sel >> 1) << 3)) * 2);
    return tb + SWZ128(off);
}
__device__ __forceinline__ uint32_t addr_B(uint32_t tb, int n0, int k0, int lane) {
    int r = lane & 7, sel = (lane >> 3) & 1;
    uint32_t off = (uint32_t)((n0 + r) * 128 + (k0 + sel * 8) * 2);
    return tb + SWZ128(off);
}

__device__ float  g_csq[NUM_K];
__device__ __half g_cbh[NUM_K * DIM_C];
__device__ __half g_cbl[NUM_K * DIM_C];

// ---------------------------------------------------------------------------
__global__ void vq_csq_kernel(const float* __restrict__ cb) {
    int k = threadIdx.x;
    const float4* row = reinterpret_cast<const float4*>(cb + k * DIM_C);
    double s = 0.0;
    #pragma unroll
    for (int i = 0; i < DIM_C / 4; i++) {
        float4 v = row[i];
        s += (double)v.x * v.x + (double)v.y * v.y + (double)v.z * v.z + (double)v.w * v.w;
    }
    g_csq[k] = (float)s;
}

__global__ void vq_prep_cb(const float* __restrict__ cb) {
    int i = blockIdx.x * 256 + threadIdx.x;
    float v = cb[i] * 512.0f;
    __half h = __float2half_rn(v);
    g_cbh[i] = h;
    g_cbl[i] = __float2half_rn(v - __half2float(h));
}

// ---------------------------------------------------------------------------
__global__ __launch_bounds__(256, 1) void vq_mma_kernel(
    const float* __restrict__ z,
    const float* __restrict__ cb,
    float* __restrict__ out,
    int write_idx)
{
    extern __shared__ char smraw[];
    uint32_t sm0 = smem_u32(smraw);
    uint32_t base = (sm0 + 1023u) & ~1023u;
    char* sm = smraw + (base - sm0);

    float* sZ   = reinterpret_cast<float*>(sm + OFF_ZST);
    float* sCSQ = reinterpret_cast<float*>(sm + OFF_CSQ);
    float* sZSQ = reinterpret_cast<float*>(sm + OFF_ZSQ);
    float* sRD  = reinterpret_cast<float*>(sm + OFF_RD);
    float* sR2  = reinterpret_cast<float*>(sm + OFF_R2);
    int*   sRK  = reinterpret_cast<int*>  (sm + OFF_RK);
    int*   sBK  = reinterpret_cast<int*>  (sm + OFF_BK);
    int*   sFlagCnt  = reinterpret_cast<int*>(sm + OFF_FLG);
    int*   sFlagList = sFlagCnt + 1;

    const int tid  = threadIdx.x;
    const int wid  = tid >> 5, lane = tid & 31;
    const int qr   = lane >> 2, qc = lane & 3;
    const int mgrp = wid >> 2, ngrp = wid & 3;     // 2 M-warps x 4 N-warps
    const int mbase  = mgrp * 64;
    const int nwbase = ngrp * 128;

    // ---- Load split codebook (SW128) + csq, once. ----
    {
        const uint4* srcH = reinterpret_cast<const uint4*>(g_cbh);
        const uint4* srcL = reinterpret_cast<const uint4*>(g_cbl);
        for (int i = tid; i < 4096; i += 256) {
            uint32_t off = (uint32_t)i * 16u;
            *reinterpret_cast<uint4*>(sm + OFF_BH + SWZ128(off)) = srcH[i];
            *reinterpret_cast<uint4*>(sm + OFF_BL + SWZ128(off)) = srcL[i];
        }
        for (int i = tid; i < NUM_K; i += 256) sCSQ[i] = g_csq[i];
    }

    for (int t = blockIdx.x; t < NTILES; t += gridDim.x) {
        const int n0t = t * PTS_TILE, b = n0t >> 12, hw0 = n0t & 4095;
        const float* zb = z + (size_t)b * (DIM_C * HW) + hw0;

        __syncthreads();
        // ---- Stage fp32 z slab [64c][128p], coalesced. ----
        for (int i = tid; i < 2048; i += 256) {
            int c = i >> 5, p4 = (i & 31) * 4;
            float4 v = *reinterpret_cast<const float4*>(zb + (size_t)c * HW + p4);
            *reinterpret_cast<float4*>(sZ + c * 128 + p4) = v;
        }
        __syncthreads();

        // ---- zsq (fp64, correctly rounded): 2 threads/point. ----
        {
            int p = tid >> 1, hf = tid & 1;
            double s = 0.0;
            for (int c = hf * 32; c < hf * 32 + 32; c++) {
                float v = sZ[c * 128 + p];
                s += (double)v * v;
            }
            double o = __shfl_xor_sync(0xffffffffu, s, 1);
            if (hf == 0) sZSQ[p] = (float)(s + o);
        }
        // ---- Build A_hi / A_lo (fp16 split, SW128 [point][channel]). ----
        {
            int p = tid & 127, ch = (tid >> 7) * 32;
            #pragma unroll
            for (int j = 0; j < 16; j++) {
                int c0 = ch + 2 * j;
                float v0 = sZ[c0 * 128 + p], v1 = sZ[(c0 + 1) * 128 + p];
                __half h0 = __float2half_rn(v0), h1 = __float2half_rn(v1);
                __half l0 = __float2half_rn(v0 - __half2float(h0));
                __half l1 = __float2half_rn(v1 - __half2float(h1));
                uint32_t boff = (uint32_t)(p * 128 + c0 * 2);
                *reinterpret_cast<__half2*>(sm + OFF_AH + SWZ128(boff)) = __halves2half2(h0, h1);
                *reinterpret_cast<__half2*>(sm + OFF_AL + SWZ128(boff)) = __halves2half2(l0, l1);
            }
        }
        if (tid == 0) *sFlagCnt = 0;
        __syncthreads();

        float zq[8];
        #pragma unroll
        for (int i = 0; i < 8; i++)
            zq[i] = sZSQ[mbase + (i >> 1) * 16 + qr + (i & 1) * 8];

        float best[8], sec[8]; int bk[8];
        #pragma unroll
        for (int i = 0; i < 8; i++) { best[i] = 3.402823466e38f; sec[i] = 3.402823466e38f; bk[i] = 0; }

        // ---- GEMM: warp covers 64 pts x 128 codes, N-chunks of 32. ----
        #pragma unroll 1
        for (int cc = 0; cc < 4; cc++) {
            float acc[4][4][4];
            #pragma unroll
            for (int mt = 0; mt < 4; mt++)
                #pragma unroll
                for (int nt = 0; nt < 4; nt++)
                    #pragma unroll
                    for (int r = 0; r < 4; r++) acc[mt][nt][r] = 0.0f;

            const int nb = nwbase + cc * 32;
            #pragma unroll
            for (int ks = 0; ks < 4; ks++) {
                const int k0 = ks * 16;
                uint32_t ah[4][4], al[4][4], bh[4][2], bl[4][2];
                #pragma unroll
                for (int mt = 0; mt < 4; mt++) {
                    ldsm_x4(ah[mt], addr_A(base + OFF_AH, mbase + mt * 16, k0, lane));
                    ldsm_x4(al[mt], addr_A(base + OFF_AL, mbase + mt * 16, k0, lane));
                }
                #pragma unroll
                for (int nt = 0; nt < 4; nt++) {
                    ldsm_x2(bh[nt], addr_B(base + OFF_BH, nb + nt * 8, k0, lane));
                    ldsm_x2(bl[nt], addr_B(base + OFF_BL, nb + nt * 8, k0, lane));
                }
                #pragma unroll
                for (int mt = 0; mt < 4; mt++)
                    #pragma unroll
                    for (int nt = 0; nt < 4; nt++) mma16816(acc[mt][nt], ah[mt], bh[nt]);
                #pragma unroll
                for (int mt = 0; mt < 4; mt++)
                    #pragma unroll
                    for (int nt = 0; nt < 4; nt++) mma16816(acc[mt][nt], ah[mt], bl[nt]);
                #pragma unroll
                for (int mt = 0; mt < 4; mt++)
                    #pragma unroll
                    for (int nt = 0; nt < 4; nt++) mma16816(acc[mt][nt], al[mt], bh[nt]);
            }

            // ---- Fold distances (ascending k within thread; track top-2). ----
            #pragma unroll
            for (int mt = 0; mt < 4; mt++) {
                #pragma unroll
                for (int nt = 0; nt < 4; nt++) {
                    int n0 = nb + nt * 8 + 2 * qc;
                    float cs0 = sCSQ[n0], cs1 = sCSQ[n0 + 1];
                    #pragma unroll
                    for (int h = 0; h < 2; h++) {       // 0: rows qr, 1: rows qr+8
                        int s = mt * 2 + h;
                        float da = __fadd_rn(__fadd_rn(zq[s], cs0), -acc[mt][nt][2 * h] * 0.00390625f);
                        float db = __fadd_rn(__fadd_rn(zq[s], cs1), -acc[mt][nt][2 * h + 1] * 0.00390625f);
                        if (da < best[s]) { sec[s] = best[s]; best[s] = da; bk[s] = n0; }
                        else if (da < sec[s]) sec[s] = da;
                        if (db < best[s]) { sec[s] = best[s]; best[s] = db; bk[s] = n0 + 1; }
                        else if (db < sec[s]) sec[s] = db;
                    }
                }
            }
        }

        // ---- Quad reduce (lanes sharing qr): merge (d1,k1,d2) triples. ----
        #pragma unroll
        for (int i = 0; i < 8; i++) {
            float d1 = best[i], d2 = sec[i]; int k1 = bk[i];
            #pragma unroll
            for (int ofs = 1; ofs <= 2; ofs <<= 1) {
                float od1 = __shfl_xor_sync(0xffffffffu, d1, ofs);
                int   ok1 = __shfl_xor_sync(0xffffffffu, k1, ofs);
                float od2 = __shfl_xor_sync(0xffffffffu, d2, ofs);
                if (od1 < d1 || (od1 == d1 && ok1 < k1)) {
                    d2 = fminf(od2, d1); d1 = od1; k1 = ok1;
                } else {
                    d2 = fminf(d2, od1);
                }
            }
            if (qc == 0) {
                int row = mbase + (i >> 1) * 16 + qr + (i & 1) * 8;
                sRD[row * 4 + ngrp] = d1;
                sRK[row * 4 + ngrp] = k1;
                sR2[row * 4 + ngrp] = d2;
            }
        }
        __syncthreads();

        // ---- Merge 4 N-warps; flag near-ties for exact rescore. ----
        if (tid < PTS_TILE) {
            float d1 = sRD[tid * 4], d2 = sR2[tid * 4]; int k1 = sRK[tid * 4];
            #pragma unroll
            for (int r = 1; r < 4; r++) {
                float od1 = sRD[tid * 4 + r], od2 = sR2[tid * 4 + r];
                int   ok1 = sRK[tid * 4 + r];
                if (od1 < d1 || (od1 == d1 && ok1 < k1)) {
                    d2 = fminf(od2, d1); d1 = od1; k1 = ok1;
                } else {
                    d2 = fminf(d2, od1);
                }
            }
            sBK[tid] = k1;
            if (d2 - d1 <= THRESH) {
                int pos = atomicAdd(sFlagCnt, 1);
                sFlagList[pos] = tid;
            }
        }
        __syncthreads();

        // ---- Exact fp32 rescore of flagged points (round-1 formula). ----
        {
            int cnt = *sFlagCnt;
            const float4* cbg = reinterpret_cast<const float4*>(cb);
            for (int f = wid; f < cnt; f += 8) {
                int p = sFlagList[f];
                float zsqp = sZSQ[p];
                float bd = 3.402823466e38f; int bkk = 0;
                for (int i = 0; i < 16; i++) {
                    int k = lane * 16 + i;
                    float d0 = 0.f, d1 = 0.f, d2 = 0.f, d3 = 0.f;
                    #pragma unroll
                    for (int j = 0; j < 16; j++) {
                        float4 cv = __ldg(&cbg[k * 16 + j]);
                        d0 = fmaf(sZ[(4 * j + 0) * 128 + p], cv.x, d0);
                        d1 = fmaf(sZ[(4 * j + 1) * 128 + p], cv.y, d1);
                        d2 = fmaf(sZ[(4 * j + 2) * 128 + p], cv.z, d2);
                        d3 = fmaf(sZ[(4 * j + 3) * 128 + p], cv.w, d3);
                    }
                    float dot = (d0 + d1) + (d2 + d3);
                    float d = __fadd_rn(__fadd_rn(zsqp, sCSQ[k]), -2.0f * dot);
                    if (d < bd) { bd = d; bkk = k; }
                }
                #pragma unroll
                for (int ofs = 1; ofs < 32; ofs <<= 1) {
                    float od = __shfl_xor_sync(0xffffffffu, bd, ofs);
                    int   ok = __shfl_xor_sync(0xffffffffu, bkk, ofs);
                    if (od < bd || (od == bd && ok < bkk)) { bd = od; bkk = ok; }
                }
                if (lane == 0) sBK[p] = bkk;
            }
        }
        __syncthreads();

        // ---- Writeback. ----
        if (tid < PTS_TILE) {
            int bkk = sBK[tid];
            float* op = out + (size_t)b * (DIM_C * HW) + hw0 + tid;
            const float4* crow = reinterpret_cast<const float4*>(cb + (size_t)bkk * DIM_C);
            #pragma unroll
            for (int i = 0; i < 16; i++) {
                float4 v = __ldg(&crow[i]);
                op[(size_t)(4 * i + 0) * HW] = v.x;
                op[(size_t)(4 * i + 1) * HW] = v.y;
                op[(size_t)(4 * i + 2) * HW] = v.z;
                op[(size_t)(4 * i + 3) * HW] = v.w;
            }
            if (write_idx) out[ZQ_ELEMS + n0t + tid] = (float)bkk;
        }
    }
}

// ---------------------------------------------------------------------------
extern "C" void kernel_launch(void* const* d_in, const int* in_sizes, int n_in,
                              void* d_out, int out_size) {
    const float* z  = (const float*)d_in[0];
    const float* cb = (const float*)d_in[1];
    float* out = (float*)d_out;

    int write_idx = (out_size >= ZQ_ELEMS + N_PTS) ? 1 : 0;

    cudaFuncSetAttribute(vq_mma_kernel,
                         cudaFuncAttributeMaxDynamicSharedMemorySize, SMEM_BYTES);

    vq_csq_kernel<<<1, NUM_K>>>(cb);
    vq_prep_cb<<<NUM_K * DIM_C / 256, 256>>>(cb);
    vq_mma_kernel<<<GRID_MAIN, 256, SMEM_BYTES>>>(z, cb, out, write_idx);
}

// round 12
// speedup vs baseline: 2.6454x; 1.2271x over previous
#include <cuda_runtime.h>
#include <cuda_fp16.h>
#include <cstdint>

// VQ-VAE vector quantizer on GB300 — single-kernel HMMA fp16-split GEMM +
// score-space argmin with margin-gated exact fp32 rescore.
//   z_e:      [32, 64, 64, 64] fp32  (B, C, H, W)
//   codebook: [512, 64] fp32
// d_out fp32: z_q (8388608) then indices (131072, stored as float).

#define NUM_K 512
#define DIM_C 64
#define HW    4096
#define N_PTS 131072
#define ZQ_ELEMS 8388608
#define PTS_TILE 128
#define NTILES   (N_PTS / PTS_TILE)
#define GRID_MAIN 148
#define THRESH 6e-5f

// smem offsets from 1024-aligned base
#define OFF_AH   0          // A_hi 128x64 fp16 SW128 : 16384
#define OFF_AL   16384      // A_lo                    : 16384
#define OFF_BH   32768      // B_hi 512x64 fp16 SW128  : 65536
#define OFF_BL   98304      // B_lo                    : 65536
#define OFF_ZST  163840     // fp32 z stage [64c][128p]: 32768
#define OFF_CSQ  196608     // 512 f  : 2048
#define OFF_RD   198656     // 128x4 f: 2048
#define OFF_R2   200704     // 128x4 f: 2048
#define OFF_RK   202752     // 128x4 i: 2048
#define OFF_BK   204800     // 128 i  : 512
#define OFF_FLG  205312     // cnt + 128 i : 520
#define SMEM_BYTES (205832 + 1024)

#define SWZ128(o) ((o) ^ ((((unsigned)(o)) >> 3) & 0x70u))

__device__ __forceinline__ uint32_t smem_u32(const void* p) {
    uint32_t a;
    asm("{ .reg .u64 t; cvta.to.shared.u64 t, %1; cvt.u32.u64 %0, t; }" : "=r"(a) : "l"(p));
    return a;
}
__device__ __forceinline__ void ldsm_x4(uint32_t* a, uint32_t addr) {
    asm volatile("ldmatrix.sync.aligned.m8n8.x4.shared.b16 {%0,%1,%2,%3}, [%4];"
        : "=r"(a[0]), "=r"(a[1]), "=r"(a[2]), "=r"(a[3]) : "r"(addr));
}
__device__ __forceinline__ void ldsm_x2(uint32_t* a, uint32_t addr) {
    asm volatile("ldmatrix.sync.aligned.m8n8.x2.shared.b16 {%0,%1}, [%2];"
        : "=r"(a[0]), "=r"(a[1]) : "r"(addr));
}
__device__ __forceinline__ void mma16816(float* c, const uint32_t* a, const uint32_t* b) {
    asm volatile("mma.sync.aligned.m16n8k16.row.col.f32.f16.f16.f32 "
        "{%0,%1,%2,%3}, {%4,%5,%6,%7}, {%8,%9}, {%0,%1,%2,%3};"
        : "+f"(c[0]), "+f"(c[1]), "+f"(c[2]), "+f"(c[3])
        : "r"(a[0]), "r"(a[1]), "r"(a[2]), "r"(a[3]), "r"(b[0]), "r"(b[1]));
}
__device__ __forceinline__ uint32_t addr_A(uint32_t tb, int m0, int k0, int lane) {
    int r = lane & 7, sel = lane >> 3;
    int row = m0 + r + ((sel & 1) << 3);
    uint32_t off = (uint32_t)(row * 128 + (k0 + ((sel >> 1) << 3)) * 2);
    return tb + SWZ128(off);
}
__device__ __forceinline__ uint32_t addr_B(uint32_t tb, int n0, int k0, int lane) {
    int r = lane & 7, sel = (lane >> 3) & 1;
    uint32_t off = (uint32_t)((n0 + r) * 128 + (k0 + sel * 8) * 2);
    return tb + SWZ128(off);
}

// ---------------------------------------------------------------------------
__global__ __launch_bounds__(256, 1) void vq_mma_kernel(
    const float* __restrict__ z,
    const float* __restrict__ cb,
    float* __restrict__ out,
    int write_idx)
{
    extern __shared__ char smraw[];
    uint32_t sm0 = smem_u32(smraw);
    uint32_t base = (sm0 + 1023u) & ~1023u;
    char* sm = smraw + (base - sm0);

    float* sZ   = reinterpret_cast<float*>(sm + OFF_ZST);
    float* sCSQ = reinterpret_cast<float*>(sm + OFF_CSQ);
    float* sRD  = reinterpret_cast<float*>(sm + OFF_RD);
    float* sR2  = reinterpret_cast<float*>(sm + OFF_R2);
    int*   sRK  = reinterpret_cast<int*>  (sm + OFF_RK);
    int*   sBK  = reinterpret_cast<int*>  (sm + OFF_BK);
    int*   sFlagCnt  = reinterpret_cast<int*>(sm + OFF_FLG);
    int*   sFlagList = sFlagCnt + 1;

    const int tid  = threadIdx.x;
    const int wid  = tid >> 5, lane = tid & 31;
    const int qr   = lane >> 2, qc = lane & 3;
    const int mgrp = wid >> 2, ngrp = wid & 3;     // 2 M-warps x 4 N-warps
    const int mbase  = mgrp * 64;
    const int nwbase = ngrp * 128;

    // ---- In-CTA prep: split codebook (x512 exact) + csq, once. ----
    {
        const float2* cb2 = reinterpret_cast<const float2*>(cb);
        for (int i = tid; i < NUM_K * DIM_C / 2; i += 256) {   // half2 units
            float2 v = __ldg(&cb2[i]);
            float a = v.x * 512.0f, bb = v.y * 512.0f;
            __half ha = __float2half_rn(a), hb = __float2half_rn(bb);
            __half la = __float2half_rn(a - __half2float(ha));
            __half lb = __float2half_rn(bb - __half2float(hb));
            uint32_t boff = (uint32_t)i * 4u;
            *reinterpret_cast<__half2*>(sm + OFF_BH + SWZ128(boff)) = __halves2half2(ha, hb);
            *reinterpret_cast<__half2*>(sm + OFF_BL + SWZ128(boff)) = __halves2half2(la, lb);
        }
        // csq in fp32 (csq ~ 8e-5; summation error ~1e-10 — negligible vs THRESH).
        for (int k = tid; k < NUM_K; k += 256) {
            const float4* row = reinterpret_cast<const float4*>(cb + k * DIM_C);
            float s0 = 0.f, s1 = 0.f, s2 = 0.f, s3 = 0.f;
            #pragma unroll
            for (int j = 0; j < 16; j++) {
                float4 v = __ldg(&row[j]);
                s0 = fmaf(v.x, v.x, s0); s1 = fmaf(v.y, v.y, s1);
                s2 = fmaf(v.z, v.z, s2); s3 = fmaf(v.w, v.w, s3);
            }
            sCSQ[k] = (s0 + s1) + (s2 + s3);
        }
    }

    for (int t = blockIdx.x; t < NTILES; t += gridDim.x) {
        const int n0t = t * PTS_TILE, b = n0t >> 12, hw0 = n0t & 4095;
        const float* zb = z + (size_t)b * (DIM_C * HW) + hw0;

        __syncthreads();
        // ---- Stage fp32 z slab [64c][128p], coalesced. ----
        for (int i = tid; i < 2048; i += 256) {
            int c = i >> 5, p4 = (i & 31) * 4;
            float4 v = *reinterpret_cast<const float4*>(zb + (size_t)c * HW + p4);
            *reinterpret_cast<float4*>(sZ + c * 128 + p4) = v;
        }
        if (tid == 0) *sFlagCnt = 0;
        __syncthreads();

        // ---- Build A_hi / A_lo (fp16 split, SW128 [point][channel]). ----
        {
            int p = tid & 127, ch = (tid >> 7) * 32;
            #pragma unroll
            for (int j = 0; j < 16; j++) {
                int c0 = ch + 2 * j;
                float v0 = sZ[c0 * 128 + p], v1 = sZ[(c0 + 1) * 128 + p];
                __half h0 = __float2half_rn(v0), h1 = __float2half_rn(v1);
                __half l0 = __float2half_rn(v0 - __half2float(h0));
                __half l1 = __float2half_rn(v1 - __half2float(h1));
                uint32_t boff = (uint32_t)(p * 128 + c0 * 2);
                *reinterpret_cast<__half2*>(sm + OFF_AH + SWZ128(boff)) = __halves2half2(h0, h1);
                *reinterpret_cast<__half2*>(sm + OFF_AL + SWZ128(boff)) = __halves2half2(l0, l1);
            }
        }
        __syncthreads();

        float best[8], sec[8]; int bk[8];
        #pragma unroll
        for (int i = 0; i < 8; i++) { best[i] = 3.402823466e38f; sec[i] = 3.402823466e38f; bk[i] = 0; }

        // ---- GEMM: warp covers 64 pts x 128 codes, N-chunks of 32. ----
        #pragma unroll 1
        for (int cc = 0; cc < 4; cc++) {
            float acc[4][4][4];
            #pragma unroll
            for (int mt = 0; mt < 4; mt++)
                #pragma unroll
                for (int nt = 0; nt < 4; nt++)
                    #pragma unroll
                    for (int r = 0; r < 4; r++) acc[mt][nt][r] = 0.0f;

            const int nb = nwbase + cc * 32;
            #pragma unroll
            for (int ks = 0; ks < 4; ks++) {
                const int k0 = ks * 16;
                uint32_t ah[4][4], al[4][4], bh[4][2], bl[4][2];
                #pragma unroll
                for (int mt = 0; mt < 4; mt++) {
                    ldsm_x4(ah[mt], addr_A(base + OFF_AH, mbase + mt * 16, k0, lane));
                    ldsm_x4(al[mt], addr_A(base + OFF_AL, mbase + mt * 16, k0, lane));
                }
                #pragma unroll
                for (int nt = 0; nt < 4; nt++) {
                    ldsm_x2(bh[nt], addr_B(base + OFF_BH, nb + nt * 8, k0, lane));
                    ldsm_x2(bl[nt], addr_B(base + OFF_BL, nb + nt * 8, k0, lane));
                }
                #pragma unroll
                for (int mt = 0; mt < 4; mt++)
                    #pragma unroll
                    for (int nt = 0; nt < 4; nt++) mma16816(acc[mt][nt], ah[mt], bh[nt]);
                #pragma unroll
                for (int mt = 0; mt < 4; mt++)
                    #pragma unroll
                    for (int nt = 0; nt < 4; nt++) mma16816(acc[mt][nt], ah[mt], bl[nt]);
                #pragma unroll
                for (int mt = 0; mt < 4; mt++)
                    #pragma unroll
                    for (int nt = 0; nt < 4; nt++) mma16816(acc[mt][nt], al[mt], bh[nt]);
            }

            // ---- Fold in SCORE space: s = csq[k] - D*2^-8 (zsq cancels). ----
            #pragma unroll
            for (int mt = 0; mt < 4; mt++) {
                #pragma unroll
                for (int nt = 0; nt < 4; nt++) {
                    int n0 = nb + nt * 8 + 2 * qc;
                    float2 cs = *reinterpret_cast<const float2*>(sCSQ + n0);
                    #pragma unroll
                    for (int h = 0; h < 2; h++) {       // 0: rows qr, 1: rows qr+8
                        int s = mt * 2 + h;
                        float da = fmaf(acc[mt][nt][2 * h],     -0.00390625f, cs.x);
                        float db = fmaf(acc[mt][nt][2 * h + 1], -0.00390625f, cs.y);
                        if (da < best[s]) { sec[s] = best[s]; best[s] = da; bk[s] = n0; }
                        else if (da < sec[s]) sec[s] = da;
                        if (db < best[s]) { sec[s] = best[s]; best[s] = db; bk[s] = n0 + 1; }
                        else if (db < sec[s]) sec[s] = db;
                    }
                }
            }
        }

        // ---- Quad reduce (lanes sharing qr): merge (d1,k1,d2) triples. ----
        #pragma unroll
        for (int i = 0; i < 8; i++) {
            float d1 = best[i], d2 = sec[i]; int k1 = bk[i];
            #pragma unroll
            for (int ofs = 1; ofs <= 2; ofs <<= 1) {
                float od1 = __shfl_xor_sync(0xffffffffu, d1, ofs);
                int   ok1 = __shfl_xor_sync(0xffffffffu, k1, ofs);
                float od2 = __shfl_xor_sync(0xffffffffu, d2, ofs);
                if (od1 < d1 || (od1 == d1 && ok1 < k1)) {
                    d2 = fminf(od2, d1); d1 = od1; k1 = ok1;
                } else {
                    d2 = fminf(d2, od1);
                }
            }
            if (qc == 0) {
                int row = mbase + (i >> 1) * 16 + qr + (i & 1) * 8;
                sRD[row * 4 + ngrp] = d1;
                sRK[row * 4 + ngrp] = k1;
                sR2[row * 4 + ngrp] = d2;
            }
        }
        __syncthreads();

        // ---- Merge 4 N-warps; flag near-ties for exact rescore. ----
        if (tid < PTS_TILE) {
            float d1 = sRD[tid * 4], d2 = sR2[tid * 4]; int k1 = sRK[tid * 4];
            #pragma unroll
            for (int r = 1; r < 4; r++) {
                float od1 = sRD[tid * 4 + r], od2 = sR2[tid * 4 + r];
                int   ok1 = sRK[tid * 4 + r];
                if (od1 < d1 || (od1 == d1 && ok1 < k1)) {
                    d2 = fminf(od2, d1); d1 = od1; k1 = ok1;
                } else {
                    d2 = fminf(d2, od1);
                }
            }
            sBK[tid] = k1;
            if (d2 - d1 <= THRESH) {
                int pos = atomicAdd(sFlagCnt, 1);
                sFlagList[pos] = tid;
            }
        }
        __syncthreads();

        // ---- Exact fp32 rescore of flagged points (reference formula). ----
        {
            int cnt = *sFlagCnt;
            const float4* cbg = reinterpret_cast<const float4*>(cb);
            for (int f = wid; f < cnt; f += 8) {
                int p = sFlagList[f];
                // zsq: fp64, correctly rounded (2 channels per lane + tree).
                float za = sZ[lane * 128 + p], zbv = sZ[(lane + 32) * 128 + p];
                double zs = (double)za * za + (double)zbv * zbv;
                #pragma unroll
                for (int ofs = 16; ofs >= 1; ofs >>= 1)
                    zs += __shfl_xor_sync(0xffffffffu, zs, ofs);
                float zsqp = (float)zs;

                float bd = 3.402823466e38f; int bkk = 0;
                for (int i = 0; i < 16; i++) {
                    int k = lane * 16 + i;
                    float d0 = 0.f, d1 = 0.f, d2 = 0.f, d3 = 0.f;
                    #pragma unroll
                    for (int j = 0; j < 16; j++) {
                        float4 cv = __ldg(&cbg[k * 16 + j]);
                        d0 = fmaf(sZ[(4 * j + 0) * 128 + p], cv.x, d0);
                        d1 = fmaf(sZ[(4 * j + 1) * 128 + p], cv.y, d1);
                        d2 = fmaf(sZ[(4 * j + 2) * 128 + p], cv.z, d2);
                        d3 = fmaf(sZ[(4 * j + 3) * 128 + p], cv.w, d3);
                    }
                    float dot = (d0 + d1) + (d2 + d3);
                    float d = __fadd_rn(__fadd_rn(zsqp, sCSQ[k]), -2.0f * dot);
                    if (d < bd) { bd = d; bkk = k; }
                }
                #pragma unroll
                for (int ofs = 1; ofs < 32; ofs <<= 1) {
                    float od = __shfl_xor_sync(0xffffffffu, bd, ofs);
                    int   ok = __shfl_xor_sync(0xffffffffu, bkk, ofs);
                    if (od < bd || (od == bd && ok < bkk)) { bd = od; bkk = ok; }
                }
                if (lane == 0) sBK[p] = bkk;
            }
        }
        __syncthreads();

        // ---- Writeback. ----
        if (tid < PTS_TILE) {
            int bkk = sBK[tid];
            float* op = out + (size_t)b * (DIM_C * HW) + hw0 + tid;
            const float4* crow = reinterpret_cast<const float4*>(cb + (size_t)bkk * DIM_C);
            #pragma unroll
            for (int i = 0; i < 16; i++) {
                float4 v = __ldg(&crow[i]);
                op[(size_t)(4 * i + 0) * HW] = v.x;
                op[(size_t)(4 * i + 1) * HW] = v.y;
                op[(size_t)(4 * i + 2) * HW] = v.z;
                op[(size_t)(4 * i + 3) * HW] = v.w;
            }
            if (write_idx) out[ZQ_ELEMS + n0t + tid] = (float)bkk;
        }
    }
}

// ---------------------------------------------------------------------------
extern "C" void kernel_launch(void* const* d_in, const int* in_sizes, int n_in,
                              void* d_out, int out_size) {
    const float* z  = (const float*)d_in[0];
    const float* cb = (const float*)d_in[1];
    float* out = (float*)d_out;

    int write_idx = (out_size >= ZQ_ELEMS + N_PTS) ? 1 : 0;

    cudaFuncSetAttribute(vq_mma_kernel,
                         cudaFuncAttributeMaxDynamicSharedMemorySize, SMEM_BYTES);

    vq_mma_kernel<<<GRID_MAIN, 256, SMEM_BYTES>>>(z, cb, out, write_idx);
}

// round 13
// speedup vs baseline: 3.0687x; 1.1600x over previous
#include <cuda_runtime.h>
#include <cuda_fp16.h>
#include <cstdint>

// VQ-VAE vector quantizer on GB300 — 512-thread HMMA fp16-split GEMM +
// score-space argmin with margin-gated exact fp32 rescore.
//   z_e:      [32, 64, 64, 64] fp32  (B, C, H, W)
//   codebook: [512, 64] fp32
// d_out fp32: z_q (8388608) then indices (131072, stored as float).

#define NUM_K 512
#define DIM_C 64
#define HW    4096
#define N_PTS 131072
#define ZQ_ELEMS 8388608
#define PTS_TILE 128
#define NTILES   (N_PTS / PTS_TILE)
#define GRID_MAIN 148
#define NTHREADS 512
#define THRESH 6e-5f

// smem offsets from 1024-aligned base
#define OFF_AH   0          // A_hi [64c][128p] fp16, chunk-swizzled : 16384
#define OFF_AL   16384      // A_lo                                   : 16384
#define OFF_BH   32768      // B_hi 512x64 fp16 SW128                 : 65536
#define OFF_BL   98304      // B_lo                                   : 65536
#define OFF_CSQ  163840     // 512 f   : 2048
#define OFF_RD   165888     // 128x4 f : 2048
#define OFF_R2   167936     // 128x4 f : 2048
#define OFF_RK   169984     // 128x4 i : 2048
#define OFF_BK   172032     // 128 i   : 512
#define OFF_FLG  172544     // cnt + 128 i
#define OFF_ZSC  173568     // 16 warps x 64 f rescore scratch : 4096
#define SMEM_BYTES (177664 + 1024)

#define SWZ128(o) ((o) ^ ((((unsigned)(o)) >> 3) & 0x70u))

__device__ __forceinline__ uint32_t smem_u32(const void* p) {
    uint32_t a;
    asm("{ .reg .u64 t; cvta.to.shared.u64 t, %1; cvt.u32.u64 %0, t; }" : "=r"(a) : "l"(p));
    return a;
}
__device__ __forceinline__ void ldsm_x4_t(uint32_t* a, uint32_t addr) {
    asm volatile("ldmatrix.sync.aligned.m8n8.x4.trans.shared.b16 {%0,%1,%2,%3}, [%4];"
        : "=r"(a[0]), "=r"(a[1]), "=r"(a[2]), "=r"(a[3]) : "r"(addr));
}
__device__ __forceinline__ void ldsm_x2(uint32_t* a, uint32_t addr) {
    asm volatile("ldmatrix.sync.aligned.m8n8.x2.shared.b16 {%0,%1}, [%2];"
        : "=r"(a[0]), "=r"(a[1]) : "r"(addr));
}
__device__ __forceinline__ void mma16816(float* c, const uint32_t* a, const uint32_t* b) {
    asm volatile("mma.sync.aligned.m16n8k16.row.col.f32.f16.f16.f32 "
        "{%0,%1,%2,%3}, {%4,%5,%6,%7}, {%8,%9}, {%0,%1,%2,%3};"
        : "+f"(c[0]), "+f"(c[1]), "+f"(c[2]), "+f"(c[3])
        : "r"(a[0]), "r"(a[1]), "r"(a[2]), "r"(a[3]), "r"(b[0]), "r"(b[1]));
}
// A tile [channel][point] fp16 rows of 256B; 16B point-chunks XOR-swizzled by
// channel. ldmatrix.trans gives standard m16n8k16 A-frag register layout.
__device__ __forceinline__ uint32_t addr_At(uint32_t tb, int m0, int k0, int lane) {
    int i = lane & 7, j = lane >> 3;
    int c = k0 + i + ((j >> 1) << 3);
    int m = m0 + ((j & 1) << 3);
    return tb + (uint32_t)c * 256u + (uint32_t)((((m >> 3) ^ (c & 15)) & 15) << 4);
}
// B tile [code][channel] fp16, 128B rows, SW128.
__device__ __forceinline__ uint32_t addr_B(uint32_t tb, int n0, int k0, int lane) {
    int r = lane & 7, sel = (lane >> 3) & 1;
    uint32_t off = (uint32_t)((n0 + r) * 128 + (k0 + sel * 8) * 2);
    return tb + SWZ128(off);
}

// ---------------------------------------------------------------------------
__global__ __launch_bounds__(NTHREADS, 1) void vq_mma_kernel(
    const float* __restrict__ z,
    const float* __restrict__ cb,
    float* __restrict__ out,
    int write_idx)
{
    extern __shared__ char smraw[];
    uint32_t sm0 = smem_u32(smraw);
    uint32_t base = (sm0 + 1023u) & ~1023u;
    char* sm = smraw + (base - sm0);

    float* sCSQ = reinterpret_cast<float*>(sm + OFF_CSQ);
    float* sRD  = reinterpret_cast<float*>(sm + OFF_RD);
    float* sR2  = reinterpret_cast<float*>(sm + OFF_R2);
    int*   sRK  = reinterpret_cast<int*>  (sm + OFF_RK);
    int*   sBK  = reinterpret_cast<int*>  (sm + OFF_BK);
    int*   sFlagCnt  = reinterpret_cast<int*>(sm + OFF_FLG);
    int*   sFlagList = sFlagCnt + 1;
    float* sZC  = reinterpret_cast<float*>(sm + OFF_ZSC);

    const int tid  = threadIdx.x;
    const int wid  = tid >> 5, lane = tid & 31;
    const int qr   = lane >> 2, qc = lane & 3;
    const int mgrp = wid >> 2, ngrp = wid & 3;     // 4 M-warps x 4 N-warps
    const int mbase  = mgrp * 32;
    const int nwbase = ngrp * 128;

    // ---- One-time prep: split codebook (x512 exact) + csq. ----
    {
        const float2* cb2 = reinterpret_cast<const float2*>(cb);
        for (int i = tid; i < NUM_K * DIM_C / 2; i += NTHREADS) {   // half2 units
            float2 v = __ldg(&cb2[i]);
            float a = v.x * 512.0f, bb = v.y * 512.0f;
            __half ha = __float2half_rn(a), hb = __float2half_rn(bb);
            __half la = __float2half_rn(a - __half2float(ha));
            __half lb = __float2half_rn(bb - __half2float(hb));
            uint32_t boff = (uint32_t)i * 4u;
            *reinterpret_cast<__half2*>(sm + OFF_BH + SWZ128(boff)) = __halves2half2(ha, hb);
            *reinterpret_cast<__half2*>(sm + OFF_BL + SWZ128(boff)) = __halves2half2(la, lb);
        }
        // csq in fp32 (csq ~ 8e-5; summation error ~1e-10 — negligible vs THRESH).
        if (tid < NUM_K) {
            int k = tid;
            const float4* row = reinterpret_cast<const float4*>(cb + k * DIM_C);
            float s0 = 0.f, s1 = 0.f, s2 = 0.f, s3 = 0.f;
            #pragma unroll
            for (int j = 0; j < 16; j++) {
                float4 v = __ldg(&row[j]);
                s0 = fmaf(v.x, v.x, s0); s1 = fmaf(v.y, v.y, s1);
                s2 = fmaf(v.z, v.z, s2); s3 = fmaf(v.w, v.w, s3);
            }
            sCSQ[k] = (s0 + s1) + (s2 + s3);
        }
    }

    for (int t = blockIdx.x; t < NTILES; t += gridDim.x) {
        const int n0t = t * PTS_TILE, b = n0t >> 12, hw0 = n0t & 4095;
        const float* zb = z + (size_t)b * (DIM_C * HW) + hw0;

        __syncthreads();   // A tiles / reduction arrays free from previous tile
        // ---- Stage + build A_hi/A_lo in one pass (global -> fp16 split). ----
        #pragma unroll
        for (int j = 0; j < 4; j++) {
            int i = tid + j * NTHREADS;           // 2048 float4 total
            int c = i >> 5, p4 = (i & 31) * 4;
            float4 v = *reinterpret_cast<const float4*>(zb + (size_t)c * HW + p4);
            __half h0 = __float2half_rn(v.x), h1 = __float2half_rn(v.y);
            __half h2 = __float2half_rn(v.z), h3 = __float2half_rn(v.w);
            __half l0 = __float2half_rn(v.x - __half2float(h0));
            __half l1 = __float2half_rn(v.y - __half2float(h1));
            __half l2 = __float2half_rn(v.z - __half2float(h2));
            __half l3 = __float2half_rn(v.w - __half2float(h3));
            uint32_t aoff = (uint32_t)c * 256u
                          + (uint32_t)(((((p4 >> 3) ^ c) & 15) << 4))
                          + (uint32_t)((p4 & 7) * 2);
            __half2 hi01 = __halves2half2(h0, h1), hi23 = __halves2half2(h2, h3);
            __half2 lo01 = __halves2half2(l0, l1), lo23 = __halves2half2(l2, l3);
            uint2 hw_, lw_;
            hw_.x = *reinterpret_cast<uint32_t*>(&hi01);
            hw_.y = *reinterpret_cast<uint32_t*>(&hi23);
            lw_.x = *reinterpret_cast<uint32_t*>(&lo01);
            lw_.y = *reinterpret_cast<uint32_t*>(&lo23);
            *reinterpret_cast<uint2*>(sm + OFF_AH + aoff) = hw_;
            *reinterpret_cast<uint2*>(sm + OFF_AL + aoff) = lw_;
        }
        if (tid == 0) *sFlagCnt = 0;
        __syncthreads();

        float best[4], sec[4]; int bk[4];
        #pragma unroll
        for (int i = 0; i < 4; i++) { best[i] = 3.402823466e38f; sec[i] = 3.402823466e38f; bk[i] = 0; }

        // ---- GEMM: warp covers 32 pts x 128 codes, N-chunks of 32. ----
        #pragma unroll 1
        for (int cc = 0; cc < 4; cc++) {
            float acc[2][4][4];
            #pragma unroll
            for (int mt = 0; mt < 2; mt++)
                #pragma unroll
                for (int nt = 0; nt < 4; nt++)
                    #pragma unroll
                    for (int r = 0; r < 4; r++) acc[mt][nt][r] = 0.0f;

            const int nb = nwbase + cc * 32;
            #pragma unroll
            for (int ks = 0; ks < 4; ks++) {
                const int k0 = ks * 16;
                uint32_t ah[2][4], al[2][4], bh[4][2], bl[4][2];
                #pragma unroll
                for (int mt = 0; mt < 2; mt++) {
                    ldsm_x4_t(ah[mt], addr_At(base + OFF_AH, mbase + mt * 16, k0, lane));
                    ldsm_x4_t(al[mt], addr_At(base + OFF_AL, mbase + mt * 16, k0, lane));
                }
                #pragma unroll
                for (int nt = 0; nt < 4; nt++) {
                    ldsm_x2(bh[nt], addr_B(base + OFF_BH, nb + nt * 8, k0, lane));
                    ldsm_x2(bl[nt], addr_B(base + OFF_BL, nb + nt * 8, k0, lane));
                }
                #pragma unroll
                for (int mt = 0; mt < 2; mt++)
                    #pragma unroll
                    for (int nt = 0; nt < 4; nt++) mma16816(acc[mt][nt], ah[mt], bh[nt]);
                #pragma unroll
                for (int mt = 0; mt < 2; mt++)
                    #pragma unroll
                    for (int nt = 0; nt < 4; nt++) mma16816(acc[mt][nt], ah[mt], bl[nt]);
                #pragma unroll
                for (int mt = 0; mt < 2; mt++)
                    #pragma unroll
                    for (int nt = 0; nt < 4; nt++) mma16816(acc[mt][nt], al[mt], bh[nt]);
            }

            // ---- Fold in SCORE space: s = csq[k] - D*2^-8 (zsq cancels). ----
            #pragma unroll
            for (int mt = 0; mt < 2; mt++) {
                #pragma unroll
                for (int nt = 0; nt < 4; nt++) {
                    int n0 = nb + nt * 8 + 2 * qc;
                    float2 cs = *reinterpret_cast<const float2*>(sCSQ + n0);
                    #pragma unroll
                    for (int h = 0; h < 2; h++) {       // 0: rows qr, 1: rows qr+8
                        int s = mt * 2 + h;
                        float da = fmaf(acc[mt][nt][2 * h],     -0.00390625f, cs.x);
                        float db = fmaf(acc[mt][nt][2 * h + 1], -0.00390625f, cs.y);
                        if (da < best[s]) { sec[s] = best[s]; best[s] = da; bk[s] = n0; }
                        else if (da < sec[s]) sec[s] = da;
                        if (db < best[s]) { sec[s] = best[s]; best[s] = db; bk[s] = n0 + 1; }
                        else if (db < sec[s]) sec[s] = db;
                    }
                }
            }
        }

        // ---- Quad reduce (lanes sharing qr): merge (d1,k1,d2) triples. ----
        #pragma unroll
        for (int i = 0; i < 4; i++) {
            float d1 = best[i], d2 = sec[i]; int k1 = bk[i];
            #pragma unroll
            for (int ofs = 1; ofs <= 2; ofs <<= 1) {
                float od1 = __shfl_xor_sync(0xffffffffu, d1, ofs);
                int   ok1 = __shfl_xor_sync(0xffffffffu, k1, ofs);
                float od2 = __shfl_xor_sync(0xffffffffu, d2, ofs);
                if (od1 < d1 || (od1 == d1 && ok1 < k1)) {
                    d2 = fminf(od2, d1); d1 = od1; k1 = ok1;
                } else {
                    d2 = fminf(d2, od1);
                }
            }
            if (qc == 0) {
                int row = mbase + (i >> 1) * 16 + qr + (i & 1) * 8;
                sRD[row * 4 + ngrp] = d1;
                sRK[row * 4 + ngrp] = k1;
                sR2[row * 4 + ngrp] = d2;
            }
        }
        __syncthreads();

        // ---- Merge 4 N-warps; flag near-ties for exact rescore. ----
        if (tid < PTS_TILE) {
            float d1 = sRD[tid * 4], d2 = sR2[tid * 4]; int k1 = sRK[tid * 4];
            #pragma unroll
            for (int r = 1; r < 4; r++) {
                float od1 = sRD[tid * 4 + r], od2 = sR2[tid * 4 + r];
                int   ok1 = sRK[tid * 4 + r];
                if (od1 < d1 || (od1 == d1 && ok1 < k1)) {
                    d2 = fminf(od2, d1); d1 = od1; k1 = ok1;
                } else {
                    d2 = fminf(d2, od1);
                }
            }
            sBK[tid] = k1;
            if (d2 - d1 <= THRESH) {
                int pos = atomicAdd(sFlagCnt, 1);
                sFlagList[pos] = tid;
            }
        }
        __syncthreads();

        // ---- Exact fp32 rescore of flagged points (reference formula). ----
        {
            int cnt = *sFlagCnt;
            const float4* cbg = reinterpret_cast<const float4*>(cb);
            float* zs_w = sZC + wid * 64;
            for (int f = wid; f < cnt; f += 16) {
                int p = sFlagList[f];
                // Fetch z_p (64 ch) from global into per-warp scratch.
                float a0 = __ldg(&zb[(size_t)lane * HW + p]);
                float a1 = __ldg(&zb[(size_t)(lane + 32) * HW + p]);
                zs_w[lane] = a0; zs_w[lane + 32] = a1;
                __syncwarp();
                // zsq: fp64, correctly rounded.
                double zs = (double)a0 * a0 + (double)a1 * a1;
                #pragma unroll
                for (int ofs = 16; ofs >= 1; ofs >>= 1)
                    zs += __shfl_xor_sync(0xffffffffu, zs, ofs);
                float zsqp = (float)zs;

                float bd = 3.402823466e38f; int bkk = 0;
                for (int i = 0; i < 16; i++) {
                    int k = lane * 16 + i;
                    float d0 = 0.f, d1 = 0.f, d2 = 0.f, d3 = 0.f;
                    #pragma unroll
                    for (int j = 0; j < 16; j++) {
                        float4 cv = __ldg(&cbg[k * 16 + j]);
                        d0 = fmaf(zs_w[4 * j + 0], cv.x, d0);
                        d1 = fmaf(zs_w[4 * j + 1], cv.y, d1);
                        d2 = fmaf(zs_w[4 * j + 2], cv.z, d2);
                        d3 = fmaf(zs_w[4 * j + 3], cv.w, d3);
                    }
                    float dot = (d0 + d1) + (d2 + d3);
                    float d = __fadd_rn(__fadd_rn(zsqp, sCSQ[k]), -2.0f * dot);
                    if (d < bd) { bd = d; bkk = k; }
                }
                #pragma unroll
                for (int ofs = 1; ofs < 32; ofs <<= 1) {
                    float od = __shfl_xor_sync(0xffffffffu, bd, ofs);
                    int   ok = __shfl_xor_sync(0xffffffffu, bkk, ofs);
                    if (od < bd || (od == bd && ok < bkk)) { bd = od; bkk = ok; }
                }
                if (lane == 0) sBK[p] = bkk;
                __syncwarp();
            }
        }
        __syncthreads();

        // ---- Writeback. ----
        if (tid < PTS_TILE) {
            int bkk = sBK[tid];
            float* op = out + (size_t)b * (DIM_C * HW) + hw0 + tid;
            const float4* crow = reinterpret_cast<const float4*>(cb + (size_t)bkk * DIM_C);
            #pragma unroll
            for (int i = 0; i < 16; i++) {
                float4 v = __ldg(&crow[i]);
                op[(size_t)(4 * i + 0) * HW] = v.x;
                op[(size_t)(4 * i + 1) * HW] = v.y;
                op[(size_t)(4 * i + 2) * HW] = v.z;
                op[(size_t)(4 * i + 3) * HW] = v.w;
            }
            if (write_idx) out[ZQ_ELEMS + n0t + tid] = (float)bkk;
        }
    }
}

// ---------------------------------------------------------------------------
extern "C" void kernel_launch(void* const* d_in, const int* in_sizes, int n_in,
                              void* d_out, int out_size) {
    const float* z  = (const float*)d_in[0];
    const float* cb = (const float*)d_in[1];
    float* out = (float*)d_out;

    int write_idx = (out_size >= ZQ_ELEMS + N_PTS) ? 1 : 0;

    cudaFuncSetAttribute(vq_mma_kernel,
                         cudaFuncAttributeMaxDynamicSharedMemorySize, SMEM_BYTES);

    vq_mma_kernel<<<GRID_MAIN, NTHREADS, SMEM_BYTES>>>(z, cb, out, write_idx);
}